// round 17
// baseline (speedup 1.0000x reference)
#include <cuda_runtime.h>

#define D 128
#define KN 32
#define MAXB 20000
#define GROWS 80           // rows per gemm block
#define GP2 82             // padded row-dim (in u64) for packed agg tile

__device__ float g_u[D];
__device__ float g_v[D];
// M stored d-pair-packed AND column-permuted:
//   u64-col c of d2-row lives at perm(c) = (c&3)*32 + (c>>2)
__device__ float g_M[D * D];
__device__ float g_agg[MAXB * D];

// packed f32x2 FMA (Blackwell): acc = a*b + acc lanewise (exact fp32, 2 lanes)
#define FMA2(acc, a, b) \
    asm("fma.rn.f32x2 %0, %1, %2, %0;" : "+l"(acc) : "l"(a), "l"(b))

// ---------------------------------------------------------------------------
// Kernel P1: u/v precompute. 2 blocks x 128 threads (measured ~2us form).
// ---------------------------------------------------------------------------
__global__ __launch_bounds__(128) void prep_uv(
    const float* __restrict__ kernel0,
    const float* __restrict__ kernel1,
    const float* __restrict__ aw) {
    int t    = threadIdx.x;
    int lane = t & 31;
    int w    = t >> 5;

    const float* mat = (blockIdx.x == 0) ? kernel1 : kernel0;
    const float* a   = aw + blockIdx.x * D;
    float*       out = (blockIdx.x == 0) ? g_u : g_v;

    float4 av = ((const float4*)a)[lane];
    const float4* m4 = (const float4*)mat;
#pragma unroll
    for (int j = 0; j < 32; ++j) {
        int r = w * 32 + j;
        float4 x = m4[r * 32 + lane];
        float s = x.x * av.x + x.y * av.y + x.z * av.z + x.w * av.w;
#pragma unroll
        for (int o = 16; o > 0; o >>= 1) s += __shfl_xor_sync(0xffffffffu, s, o);
        if (lane == 0) out[r] = s;
    }
}

// ---------------------------------------------------------------------------
// Kernel P2: M precompute (measured form), d-pair-packed + column-permuted.
// Runs on a forked stream, concurrent with attn (independent outputs).
// ---------------------------------------------------------------------------
__global__ __launch_bounds__(128) void prep_M(
    const float* __restrict__ kernel1,
    const float* __restrict__ nw) {
    extern __shared__ float psm[];
    float* nws  = psm;          // D*D floats (64KB)
    float* krow = psm + D * D;  // D floats

    int b = blockIdx.x;
    int t = threadIdx.x;

    krow[t] = kernel1[b * D + t];
    const float4* nw4  = (const float4*)nw;
    float4*       nws4 = (float4*)nws;
#pragma unroll
    for (int it = 0; it < 32; ++it)
        nws4[it * 128 + t] = nw4[it * 128 + t];
    __syncthreads();

    float acc = 0.f;
#pragma unroll 16
    for (int j = 0; j < D; ++j)
        acc += krow[j] * nws[j * D + t];
    int perm = (t & 3) * 32 + (t >> 2);      // u64-column permutation
    g_M[(b >> 1) * 256 + perm * 2 + (b & 1)] = acc;
}

// ---------------------------------------------------------------------------
// Kernel A (R15-measured): streaming softmax, register-resident rows.
// ---------------------------------------------------------------------------
__global__ __launch_bounds__(128) void attn_kernel(
    const float* __restrict__ features,
    const int* __restrict__ node,
    const int* __restrict__ neigh,
    int B) {
    __shared__ float part[4 * D];
    __shared__ float esums[4];

    int b = blockIdx.x;
    if (b >= B) return;
    int tid  = threadIdx.x;
    int lane = tid & 31;
    int w    = tid >> 5;

    const float4* f4 = (const float4*)features;

    int nv = __ldg(&neigh[b * KN + lane]);
    int nd = __ldg(&node[b]);

    float4 x[8];
#pragma unroll
    for (int it = 0; it < 8; ++it) {
        int k  = it * 4 + w;
        int nb = __shfl_sync(0xffffffffu, nv, k);
        x[it]  = f4[(size_t)nb * 32 + lane];
    }

    float4 fv = f4[(size_t)nd * 32 + lane];
    float4 vv = ((const float4*)g_v)[lane];
    float sn = fv.x * vv.x + fv.y * vv.y + fv.z * vv.z + fv.w * vv.w;
#pragma unroll
    for (int o = 16; o > 0; o >>= 1) sn += __shfl_xor_sync(0xffffffffu, sn, o);

    float4 uu = ((const float4*)g_u)[lane];
    float4 p  = make_float4(0.f, 0.f, 0.f, 0.f);
    float esum = 0.f;
#pragma unroll
    for (int it = 0; it < 8; ++it) {
        float s = x[it].x * uu.x + x[it].y * uu.y + x[it].z * uu.z + x[it].w * uu.w;
#pragma unroll
        for (int o = 16; o > 0; o >>= 1) s += __shfl_xor_sync(0xffffffffu, s, o);
        float t = s + sn;
        t = (t > 0.f) ? t : 0.2f * t;          // leaky_relu
        float e = __expf(t);
        esum += e;
        p.x += e * x[it].x;
        p.y += e * x[it].y;
        p.z += e * x[it].z;
        p.w += e * x[it].w;
    }
    ((float4*)part)[w * 32 + lane] = p;
    if (lane == 0) esums[w] = esum;
    __syncthreads();

    float total = esums[0] + esums[1] + esums[2] + esums[3];
    float acc = part[tid] + part[D + tid] + part[2 * D + tid] + part[3 * D + tid];
    g_agg[b * D + tid] = acc / total;
}

// ---------------------------------------------------------------------------
// Kernel G v9: 320 threads (20 ty x 16 tx), block = 80 rows, 4x4x2 thread
// tile, FMA2, conflict-free permuted m-loads. smem 106KB -> 2 blocks/SM
// (20 warps/SM = 5/SMSP). Grid 250.
// ---------------------------------------------------------------------------
__global__ __launch_bounds__(320, 2) void out_gemm(float* __restrict__ out, int B) {
    extern __shared__ float sm[];
    unsigned long long* Msp  = (unsigned long long*)sm;   // [64 d2][128 c] permuted
    unsigned long long* aTsp = Msp + 64 * D;              // [64 d2][GP2 rows]

    int tid = threadIdx.x;
    int r0  = blockIdx.x * GROWS;

    // stage packed M
    {
        float4*       s4 = (float4*)Msp;
        const float4* g4 = (const float4*)g_M;
        for (int i = tid; i < (D * D) / 4; i += 320) s4[i] = g4[i];
    }

    // stage agg tile d-pair packed: 4 threads per row, each covers 32 d (16 d2)
    {
        int row = tid >> 2;            // 0..79
        int q   = tid & 3;
        bool rv = (r0 + row) < B;
        const float4* ga = (const float4*)g_agg + (size_t)(r0 + row) * 32 + q * 8;
#pragma unroll
        for (int i = 0; i < 8; ++i) {
            float4 f = rv ? ga[i] : make_float4(0.f, 0.f, 0.f, 0.f);
            int d2 = q * 16 + i * 2;
            unsigned long long p01, p23;
            asm("mov.b64 %0, {%1, %2};" : "=l"(p01) : "f"(f.x), "f"(f.y));
            asm("mov.b64 %0, {%1, %2};" : "=l"(p23) : "f"(f.z), "f"(f.w));
            aTsp[(d2 + 0) * GP2 + row] = p01;
            aTsp[(d2 + 1) * GP2 + row] = p23;
        }
    }
    __syncthreads();

    int ty = tid >> 4;   // 0..19 -> rows ty*4..ty*4+3
    int tx = tid & 15;   // 0..15 -> cols h*64 + tx*4 .. +3 (logical)

#pragma unroll
    for (int h = 0; h < 2; ++h) {
        unsigned long long acc[4][4];
#pragma unroll
        for (int i = 0; i < 4; ++i)
#pragma unroll
            for (int j = 0; j < 4; ++j) acc[i][j] = 0ull;

#pragma unroll 8
        for (int d2 = 0; d2 < 64; ++d2) {
            const unsigned long long* ar = aTsp + d2 * GP2 + ty * 4;
            ulonglong2 a01 = *(const ulonglong2*)(ar);
            ulonglong2 a23 = *(const ulonglong2*)(ar + 2);
            const unsigned long long* mr = Msp + d2 * D + h * 16 + tx;
            unsigned long long m_[4] = { mr[0], mr[32], mr[64], mr[96] };
            unsigned long long a_[4] = { a01.x, a01.y, a23.x, a23.y };
#pragma unroll
            for (int i = 0; i < 4; ++i) {
#pragma unroll
                for (int j = 0; j < 4; ++j) FMA2(acc[i][j], a_[i], m_[j]);
            }
        }

#pragma unroll
        for (int i = 0; i < 4; ++i) {
            int row = r0 + ty * 4 + i;
            if (row < B) {
                float r_[4];
#pragma unroll
                for (int j = 0; j < 4; ++j) {
                    float lo, hi;
                    asm("mov.b64 {%0, %1}, %2;" : "=f"(lo), "=f"(hi) : "l"(acc[i][j]));
                    r_[j] = lo + hi;
                }
                *(float4*)(out + (size_t)row * D + h * 64 + tx * 4) =
                    make_float4(r_[0], r_[1], r_[2], r_[3]);
            }
        }
    }
}

// ---------------------------------------------------------------------------
extern "C" void kernel_launch(void* const* d_in, const int* in_sizes, int n_in,
                              void* d_out, int out_size) {
    const float* features = (const float*)d_in[0];
    const int*   node     = (const int*)d_in[1];
    const int*   neigh    = (const int*)d_in[2];
    const float* kern0    = (const float*)d_in[3];
    const float* kern1    = (const float*)d_in[4];
    const float* aw       = (const float*)d_in[5];
    const float* nw       = (const float*)d_in[6];
    float*       out      = (float*)d_out;

    int B = in_sizes[1];
    if (B > MAXB) B = MAXB;

    // one-time side stream + events (host objects only; no device allocs)
    static cudaStream_t s2 = nullptr;
    static cudaEvent_t ev_fork = nullptr, ev_join = nullptr;
    if (s2 == nullptr) {
        cudaStreamCreateWithFlags(&s2, cudaStreamNonBlocking);
        cudaEventCreateWithFlags(&ev_fork, cudaEventDisableTiming);
        cudaEventCreateWithFlags(&ev_join, cudaEventDisableTiming);
    }

    // 1: u,v (attn dependency) on main stream
    prep_uv<<<2, D>>>(kern0, kern1, aw);

    // fork: prep_M runs concurrently with attn (only gemm needs g_M)
    cudaEventRecord(ev_fork, 0);
    cudaStreamWaitEvent(s2, ev_fork, 0);
    const int prepM_smem = (D * D + D) * sizeof(float);        // ~66 KB
    cudaFuncSetAttribute(prep_M, cudaFuncAttributeMaxDynamicSharedMemorySize, prepM_smem);
    prep_M<<<D, D, prepM_smem, s2>>>(kern1, nw);               // 2 (side stream)

    attn_kernel<<<B, D>>>(features, node, neigh, B);           // 3 (main)

    // join: gemm needs both g_M and g_agg
    cudaEventRecord(ev_join, s2);
    cudaStreamWaitEvent(0, ev_join, 0);

    const int gemm_smem = (64 * D + 64 * GP2) * 8;             // ~106 KB
    cudaFuncSetAttribute(out_gemm, cudaFuncAttributeMaxDynamicSharedMemorySize, gemm_smem);
    int gblocks = (B + GROWS - 1) / GROWS;                     // 250
    out_gemm<<<gblocks, 320, gemm_smem>>>(out, B);             // 4 (profiled)
}